// round 15
// baseline (speedup 1.0000x reference)
#include <cuda_runtime.h>
#include <cuda_fp16.h>
#include <cstdint>

#define HID  256
#define QN   200
#define NPIX (256 * 256)
#define NB   4
#define NROW (NB * QN)    // 800 merged (b,q) rows

#define MROWS   13        // ceil(200/16) query row-tiles of 16
#define KSTEPS  16        // 256 / 16
#define PTILE   64        // pixels per GEMM tile
#define TTILES  4         // tiles per CTA (cp.async pipeline depth in time)
#define BSTRIDE 132       // smem row stride in u32 (k-pairs), conflict-free
#define NWARP   13        // one warp per m-row tile (R10 shape)
#define GTHREADS (NWARP * 32)

#define LSTRIDE 36        // layer-kernel transposed panel stride (f32)

// GEMM smem: raw fp32 staging [256 ch][64 px] + fp16 sB [64 px][BSTRIDE]
#define RAW_U32  (HID * PTILE)             // 16384 u32 = 64KB
#define SB_U32   (PTILE * BSTRIDE)         // 8448 u32  = 33KB

// ---------------------------------------------------------------------------
// Device scratch (allocation-free)
// ---------------------------------------------------------------------------
__device__ float g_h [NROW * HID];                          // hidden fp32
__device__ float g_me[NROW * HID];                          // mask_embed fp32
__device__ uint4 g_AH[NB * MROWS * KSTEPS * 32];            // A fragments (fp16)

// ---------------------------------------------------------------------------
// PTX helpers (baseline PTX, sm_100 OK)
// ---------------------------------------------------------------------------
__device__ __forceinline__ void mma_f16(float* d, uint4 a, uint32_t b0, uint32_t b1) {
    asm volatile(
        "mma.sync.aligned.m16n8k16.row.col.f32.f16.f16.f32 "
        "{%0,%1,%2,%3}, {%4,%5,%6,%7}, {%8,%9}, {%0,%1,%2,%3};"
        : "+f"(d[0]), "+f"(d[1]), "+f"(d[2]), "+f"(d[3])
        : "r"(a.x), "r"(a.y), "r"(a.z), "r"(a.w), "r"(b0), "r"(b1));
}

__device__ __forceinline__ void ldsm_x4(uint32_t& r0, uint32_t& r1,
                                        uint32_t& r2, uint32_t& r3, uint32_t addr) {
    asm volatile("ldmatrix.sync.aligned.m8n8.x4.shared.b16 {%0,%1,%2,%3}, [%4];"
        : "=r"(r0), "=r"(r1), "=r"(r2), "=r"(r3) : "r"(addr));
}

__device__ __forceinline__ void cp_async16(uint32_t saddr, const void* gaddr) {
    asm volatile("cp.async.cg.shared.global [%0], [%1], 16;"
        :: "r"(saddr), "l"(gaddr) : "memory");
}
#define CP_COMMIT() asm volatile("cp.async.commit_group;" ::: "memory")
#define CP_WAIT0()  asm volatile("cp.async.wait_group 0;" ::: "memory")

__device__ __forceinline__ uint32_t pack_f16(float a, float b) {
    __half2 h = __floats2half2_rn(a, b);
    return *reinterpret_cast<uint32_t*>(&h);
}

// ---------------------------------------------------------------------------
// MLP layer (R14, passing): full-K panels, one sync, 256-step FMA loop.
// ---------------------------------------------------------------------------
template<bool RELU>
__global__ __launch_bounds__(128) void layer_kernel(
    const float* __restrict__ A, const float* __restrict__ W,
    const float* __restrict__ bias, float* __restrict__ C)
{
    extern __shared__ float lsm[];
    float* sA = lsm;                        // [256 k][LSTRIDE rows]
    float* sW = lsm + HID * LSTRIDE;        // [256 k][LSTRIDE cols]

    const int tid = threadIdx.x;
    const int r0 = blockIdx.x * 32;
    const int n0 = blockIdx.y * 32;
    const int tr = tid & 7;
    const int tc = tid >> 3;
    const int lrow = tid >> 2;
    const int lq   = tid & 3;

    #pragma unroll
    for (int kk = 0; kk < 16; kk++) {
        const int k0 = (lq + kk * 4) * 4;
        float4 va = *reinterpret_cast<const float4*>(A + (size_t)(r0 + lrow) * HID + k0);
        sA[(k0 + 0) * LSTRIDE + lrow] = va.x;
        sA[(k0 + 1) * LSTRIDE + lrow] = va.y;
        sA[(k0 + 2) * LSTRIDE + lrow] = va.z;
        sA[(k0 + 3) * LSTRIDE + lrow] = va.w;
        float4 vw = *reinterpret_cast<const float4*>(W + (size_t)(n0 + lrow) * HID + k0);
        sW[(k0 + 0) * LSTRIDE + lrow] = vw.x;
        sW[(k0 + 1) * LSTRIDE + lrow] = vw.y;
        sW[(k0 + 2) * LSTRIDE + lrow] = vw.z;
        sW[(k0 + 3) * LSTRIDE + lrow] = vw.w;
    }
    __syncthreads();

    float acc[4][2] = {};
    #pragma unroll 8
    for (int k = 0; k < HID; k++) {
        float4 a = *reinterpret_cast<const float4*>(&sA[k * LSTRIDE + tr * 4]);
        float2 w = *reinterpret_cast<const float2*>(&sW[k * LSTRIDE + tc * 2]);
        acc[0][0] = fmaf(a.x, w.x, acc[0][0]); acc[0][1] = fmaf(a.x, w.y, acc[0][1]);
        acc[1][0] = fmaf(a.y, w.x, acc[1][0]); acc[1][1] = fmaf(a.y, w.y, acc[1][1]);
        acc[2][0] = fmaf(a.z, w.x, acc[2][0]); acc[2][1] = fmaf(a.z, w.y, acc[2][1]);
        acc[3][0] = fmaf(a.w, w.x, acc[3][0]); acc[3][1] = fmaf(a.w, w.y, acc[3][1]);
    }

    const float b0 = bias[n0 + tc * 2];
    const float b1 = bias[n0 + tc * 2 + 1];
    #pragma unroll
    for (int r = 0; r < 4; r++) {
        float v0 = acc[r][0] + b0;
        float v1 = acc[r][1] + b1;
        if (RELU) { v0 = v0 > 0.f ? v0 : 0.f; v1 = v1 > 0.f ? v1 : 0.f; }
        *reinterpret_cast<float2*>(C + (size_t)(r0 + tr * 4 + r) * HID + n0 + tc * 2)
            = make_float2(v0, v1);
    }
}

// ---------------------------------------------------------------------------
// Pack mask_embed into per-lane A fragments (single fp16 rounding).
// ---------------------------------------------------------------------------
__global__ __launch_bounds__(512) void pack_kernel()
{
    const int blk = blockIdx.x;
    const int b   = blk / MROWS;
    const int mr  = blk % MROWS;
    const int ks  = threadIdx.x >> 5;
    const int lane = threadIdx.x & 31;
    const int g = lane >> 2, i4 = lane & 3;

    const int r0 = mr * 16 + g;
    const int r1 = r0 + 8;
    const int c0 = ks * 16 + i4 * 2;

    float v[2][4];
    #pragma unroll
    for (int rr = 0; rr < 2; rr++) {
        const int r = rr ? r1 : r0;
        #pragma unroll
        for (int cc = 0; cc < 4; cc++) {
            const int c = c0 + (cc >> 1) * 8 + (cc & 1);
            v[rr][cc] = (r < QN) ? g_me[(size_t)(b * QN + r) * HID + c] : 0.f;
        }
    }

    uint4 ah;
    ah.x = pack_f16(v[0][0], v[0][1]);
    ah.y = pack_f16(v[1][0], v[1][1]);
    ah.z = pack_f16(v[0][2], v[0][3]);
    ah.w = pack_f16(v[1][2], v[1][3]);

    g_AH[((size_t)(b * MROWS + mr) * KSTEPS + ks) * 32 + lane] = ah;
}

// ---------------------------------------------------------------------------
// GEMM with cp.async pipelining: CTA processes TTILES consecutive 64-px
// tiles. While MMA(t) runs, cp.async streams tile t+1's raw fp32 into smem
// (no regs, no issue pressure) -> DRAM hidden under MMA. Convert is then a
// short LDS-fed compute pass. MMA/ldmatrix/epilogue byte-identical to R10.
// smem = raw 64KB + sB 33KB = 97.8KB -> 2 CTAs/SM.
// ---------------------------------------------------------------------------
__global__ __launch_bounds__(GTHREADS) void gemm_kernel(
    const float* __restrict__ mf, float* __restrict__ out)
{
    extern __shared__ uint32_t smem_g[];
    float*    raw = reinterpret_cast<float*>(smem_g);   // [256 ch][64 px] fp32
    uint32_t* sB  = smem_g + RAW_U32;                   // [64 px][BSTRIDE]

    const int tid  = threadIdx.x;
    const int lane = tid & 31;
    const int w    = tid >> 5;
    const int g    = lane >> 2, i4 = lane & 3;

    const int pbase = blockIdx.x * (PTILE * TTILES);
    const int b     = blockIdx.y;

    const float* mfb  = mf  + (size_t)b * HID * NPIX;
    float*       outb = out + (size_t)b * QN  * NPIX;

    const uint32_t raw_s = (uint32_t)__cvta_generic_to_shared(raw);

    // warp role (rotated); A fragment pointer
    const int mr = (w + (int)blockIdx.x) % NWARP;
    const uint4* pAH = g_AH + ((size_t)(b * MROWS + mr) * KSTEPS) * 32 + lane;

    // ldmatrix per-thread base
    const int q8 = lane >> 3;
    const int r8 = lane & 7;
    const uint32_t sB_s = (uint32_t)__cvta_generic_to_shared(sB);
    const uint32_t lm_base = sB_s +
        (uint32_t)((((q8 >> 1) * 8 + r8) * BSTRIDE + (q8 & 1) * 4) * 4);
    const uint32_t J_STRIDE = (uint32_t)(16 * BSTRIDE * 4);

    // ---- cp.async issue of one tile's raw fp32 (4096 x 16B) ----
    auto issue_tile = [&](int p0) {
        for (int c = tid; c < HID * (PTILE / 4); c += GTHREADS) {   // 4096 chunks
            const int ch  = c >> 4;            // channel 0..255
            const int px4 = c & 15;            // 16B chunk within row
            cp_async16(raw_s + (uint32_t)(ch * PTILE + px4 * 4) * 4,
                       mfb + (size_t)ch * NPIX + p0 + px4 * 4);
        }
        CP_COMMIT();
    };

    // ---- convert raw (smem fp32) -> sB (fp16, R10 layout + stagger) ----
    auto convert_tile = [&]() {
        for (int idx = tid; idx < 128 * 16; idx += GTHREADS) {
            const int cp = idx >> 4;
            const int p4 = idx & 15;
            float4 v0 = *reinterpret_cast<const float4*>(&raw[(2 * cp)     * PTILE + p4 * 4]);
            float4 v1 = *reinterpret_cast<const float4*>(&raw[(2 * cp + 1) * PTILE + p4 * 4]);
            const float a0[4] = {v0.x, v0.y, v0.z, v0.w};
            const float a1[4] = {v1.x, v1.y, v1.z, v1.w};
            #pragma unroll
            for (int s = 0; s < 4; s++) {
                const int j = (s + p4) & 3;
                sB[(uint32_t)(p4 * 4 + j) * BSTRIDE + cp] = pack_f16(a0[j], a1[j]);
            }
        }
    };

    // ---- prologue: fetch + convert tile 0 ----
    issue_tile(pbase);
    CP_WAIT0();
    __syncthreads();
    convert_tile();

    // ---- pipelined main loop ----
    for (int t = 0; t < TTILES; t++) {
        __syncthreads();                           // sB(t) ready; raw free
        if (t + 1 < TTILES) issue_tile(pbase + (t + 1) * PTILE);

        // MMA on sB (byte-identical to R10 inner loop)
        float acc[8][4];
        #pragma unroll
        for (int n = 0; n < 8; n++)
            #pragma unroll
            for (int x = 0; x < 4; x++) acc[n][x] = 0.f;

        #pragma unroll 4
        for (int ks = 0; ks < KSTEPS; ks++) {
            const uint4 ah = pAH[ks * 32];
            const uint32_t ka = lm_base + (uint32_t)(ks * 32);
            #pragma unroll
            for (int j = 0; j < 4; j++) {
                uint32_t b0, b1, b2, b3;
                ldsm_x4(b0, b1, b2, b3, ka + (uint32_t)j * J_STRIDE);
                mma_f16(acc[2 * j],     ah, b0, b1);
                mma_f16(acc[2 * j + 1], ah, b2, b3);
            }
        }

        // epilogue for tile t
        const int p0 = pbase + t * PTILE;
        {
            const int q = mr * 16 + g;
            if (q < QN) {
                float* o = outb + (size_t)q * NPIX + p0 + i4 * 2;
                #pragma unroll
                for (int nc = 0; nc < 8; nc++)
                    *reinterpret_cast<float2*>(o + nc * 8) = make_float2(acc[nc][0], acc[nc][1]);
            }
            const int q2 = q + 8;
            if (q2 < QN) {
                float* o2 = outb + (size_t)q2 * NPIX + p0 + i4 * 2;
                #pragma unroll
                for (int nc = 0; nc < 8; nc++)
                    *reinterpret_cast<float2*>(o2 + nc * 8) = make_float2(acc[nc][2], acc[nc][3]);
            }
        }

        if (t + 1 < TTILES) {
            CP_WAIT0();                            // tile t+1 raw landed
            __syncthreads();                       // all warps done reading sB(t)
            convert_tile();                        // build sB(t+1)
        }
    }
}

// ---------------------------------------------------------------------------
extern "C" void kernel_launch(void* const* d_in, const int* in_sizes, int n_in,
                              void* d_out, int out_size)
{
    const float* queries = (const float*)d_in[0];  // (4, 200, 256)
    const float* mf      = (const float*)d_in[1];  // (4, 256, 256, 256)
    const float* w1      = (const float*)d_in[2];
    const float* b1      = (const float*)d_in[3];
    const float* w2      = (const float*)d_in[4];
    const float* b2      = (const float*)d_in[5];
    float* out = (float*)d_out;                    // (4, 200, 256, 256)

    float* hbuf;  cudaGetSymbolAddress((void**)&hbuf,  g_h);
    float* mebuf; cudaGetSymbolAddress((void**)&mebuf, g_me);

    const int lsm = 2 * HID * LSTRIDE * (int)sizeof(float);     // 73728 B
    cudaFuncSetAttribute(layer_kernel<true >, cudaFuncAttributeMaxDynamicSharedMemorySize, lsm);
    cudaFuncSetAttribute(layer_kernel<false>, cudaFuncAttributeMaxDynamicSharedMemorySize, lsm);

    const int gsm = (RAW_U32 + SB_U32) * (int)sizeof(uint32_t); // 100352 B
    cudaFuncSetAttribute(gemm_kernel, cudaFuncAttributeMaxDynamicSharedMemorySize, gsm);

    layer_kernel<true ><<<dim3(NROW / 32, HID / 32), 128, lsm>>>(queries, w1, b1, hbuf);
    layer_kernel<false><<<dim3(NROW / 32, HID / 32), 128, lsm>>>(hbuf,    w2, b2, mebuf);
    pack_kernel<<<NB * MROWS, 512>>>();
    gemm_kernel<<<dim3(NPIX / (PTILE * TTILES), NB), GTHREADS, gsm>>>(mf, out);
}

// round 16
// speedup vs baseline: 1.1410x; 1.1410x over previous
#include <cuda_runtime.h>
#include <cuda_fp16.h>
#include <cstdint>

#define HID  256
#define QN   200
#define NPIX (256 * 256)
#define NB   4
#define NROW (NB * QN)    // 800 merged (b,q) rows

#define MROWS   13        // ceil(200/16) query row-tiles of 16
#define KSTEPS  16        // 256 / 16
#define PTILE   64        // pixels per GEMM CTA
#define BSTRIDE 132       // smem row stride in u32 (k-pairs), conflict-free
#define NWARP   13        // warps 0..11 dual-m, warp 12 single (tile 12)
#define GTHREADS (NWARP * 32)

#define LSTRIDE 36        // layer-kernel transposed panel stride (f32)

// ---------------------------------------------------------------------------
// Device scratch (allocation-free)
// ---------------------------------------------------------------------------
__device__ float g_h [NROW * HID];                          // hidden fp32
__device__ float g_me[NROW * HID];                          // mask_embed fp32
__device__ uint4 g_AH[NB * MROWS * KSTEPS * 32];            // A fragments (fp16)

// ---------------------------------------------------------------------------
// mma.sync m16n8k16 fp16 in / fp32 accum + ldmatrix (baseline PTX, sm_100 OK)
// ---------------------------------------------------------------------------
__device__ __forceinline__ void mma_f16(float* d, uint4 a, uint32_t b0, uint32_t b1) {
    asm volatile(
        "mma.sync.aligned.m16n8k16.row.col.f32.f16.f16.f32 "
        "{%0,%1,%2,%3}, {%4,%5,%6,%7}, {%8,%9}, {%0,%1,%2,%3};"
        : "+f"(d[0]), "+f"(d[1]), "+f"(d[2]), "+f"(d[3])
        : "r"(a.x), "r"(a.y), "r"(a.z), "r"(a.w), "r"(b0), "r"(b1));
}

__device__ __forceinline__ void ldsm_x4(uint32_t& r0, uint32_t& r1,
                                        uint32_t& r2, uint32_t& r3, uint32_t addr) {
    asm volatile("ldmatrix.sync.aligned.m8n8.x4.shared.b16 {%0,%1,%2,%3}, [%4];"
        : "=r"(r0), "=r"(r1), "=r"(r2), "=r"(r3) : "r"(addr));
}

__device__ __forceinline__ uint32_t pack_f16(float a, float b) {
    __half2 h = __floats2half2_rn(a, b);
    return *reinterpret_cast<uint32_t*>(&h);
}

// ---------------------------------------------------------------------------
// MLP layer (R14, passing): full-K panels, one sync, 256-step FMA loop.
// ---------------------------------------------------------------------------
template<bool RELU>
__global__ __launch_bounds__(128) void layer_kernel(
    const float* __restrict__ A, const float* __restrict__ W,
    const float* __restrict__ bias, float* __restrict__ C)
{
    extern __shared__ float lsm[];
    float* sA = lsm;                        // [256 k][LSTRIDE rows]
    float* sW = lsm + HID * LSTRIDE;        // [256 k][LSTRIDE cols]

    const int tid = threadIdx.x;
    const int r0 = blockIdx.x * 32;
    const int n0 = blockIdx.y * 32;
    const int tr = tid & 7;
    const int tc = tid >> 3;
    const int lrow = tid >> 2;
    const int lq   = tid & 3;

    #pragma unroll
    for (int kk = 0; kk < 16; kk++) {
        const int k0 = (lq + kk * 4) * 4;
        float4 va = *reinterpret_cast<const float4*>(A + (size_t)(r0 + lrow) * HID + k0);
        sA[(k0 + 0) * LSTRIDE + lrow] = va.x;
        sA[(k0 + 1) * LSTRIDE + lrow] = va.y;
        sA[(k0 + 2) * LSTRIDE + lrow] = va.z;
        sA[(k0 + 3) * LSTRIDE + lrow] = va.w;
        float4 vw = *reinterpret_cast<const float4*>(W + (size_t)(n0 + lrow) * HID + k0);
        sW[(k0 + 0) * LSTRIDE + lrow] = vw.x;
        sW[(k0 + 1) * LSTRIDE + lrow] = vw.y;
        sW[(k0 + 2) * LSTRIDE + lrow] = vw.z;
        sW[(k0 + 3) * LSTRIDE + lrow] = vw.w;
    }
    __syncthreads();

    float acc[4][2] = {};
    #pragma unroll 8
    for (int k = 0; k < HID; k++) {
        float4 a = *reinterpret_cast<const float4*>(&sA[k * LSTRIDE + tr * 4]);
        float2 w = *reinterpret_cast<const float2*>(&sW[k * LSTRIDE + tc * 2]);
        acc[0][0] = fmaf(a.x, w.x, acc[0][0]); acc[0][1] = fmaf(a.x, w.y, acc[0][1]);
        acc[1][0] = fmaf(a.y, w.x, acc[1][0]); acc[1][1] = fmaf(a.y, w.y, acc[1][1]);
        acc[2][0] = fmaf(a.z, w.x, acc[2][0]); acc[2][1] = fmaf(a.z, w.y, acc[2][1]);
        acc[3][0] = fmaf(a.w, w.x, acc[3][0]); acc[3][1] = fmaf(a.w, w.y, acc[3][1]);
    }

    const float b0 = bias[n0 + tc * 2];
    const float b1 = bias[n0 + tc * 2 + 1];
    #pragma unroll
    for (int r = 0; r < 4; r++) {
        float v0 = acc[r][0] + b0;
        float v1 = acc[r][1] + b1;
        if (RELU) { v0 = v0 > 0.f ? v0 : 0.f; v1 = v1 > 0.f ? v1 : 0.f; }
        *reinterpret_cast<float2*>(C + (size_t)(r0 + tr * 4 + r) * HID + n0 + tc * 2)
            = make_float2(v0, v1);
    }
}

// ---------------------------------------------------------------------------
// Pack mask_embed into per-lane A fragments (single fp16 rounding).
// ---------------------------------------------------------------------------
__global__ __launch_bounds__(512) void pack_kernel()
{
    const int blk = blockIdx.x;
    const int b   = blk / MROWS;
    const int mr  = blk % MROWS;
    const int ks  = threadIdx.x >> 5;
    const int lane = threadIdx.x & 31;
    const int g = lane >> 2, i4 = lane & 3;

    const int r0 = mr * 16 + g;
    const int r1 = r0 + 8;
    const int c0 = ks * 16 + i4 * 2;

    float v[2][4];
    #pragma unroll
    for (int rr = 0; rr < 2; rr++) {
        const int r = rr ? r1 : r0;
        #pragma unroll
        for (int cc = 0; cc < 4; cc++) {
            const int c = c0 + (cc >> 1) * 8 + (cc & 1);
            v[rr][cc] = (r < QN) ? g_me[(size_t)(b * QN + r) * HID + c] : 0.f;
        }
    }

    uint4 ah;
    ah.x = pack_f16(v[0][0], v[0][1]);
    ah.y = pack_f16(v[1][0], v[1][1]);
    ah.z = pack_f16(v[0][2], v[0][3]);
    ah.w = pack_f16(v[1][2], v[1][3]);

    g_AH[((size_t)(b * MROWS + mr) * KSTEPS + ks) * 32 + lane] = ah;
}

// ---------------------------------------------------------------------------
// GEMM: out[b,q,p] = sum_c me[b,q,c] * mf[b,c,p]
// R10 frame (CTA = 64-px stripe, 13 warps, rotation, ldmatrix layout) with
// the dual/single decision hoisted OUT of the k-loop:
//   warps 0..11 (dual): m-pair (2p,2p+1) x 4 n-chunks; per k-step
//       2 A-LDG + 2 ldsm.x4 + 8 MMA (each LDSM feeds 4 MMAs)
//   warp 12 (single):  m-tile 12 x 8 n-chunks; R10-exact loop
// LDSM bytes/CTA 416KB -> 224KB with clean straight-line inner loops.
// ---------------------------------------------------------------------------
__global__ __launch_bounds__(GTHREADS) void gemm_kernel(
    const float* __restrict__ mf, float* __restrict__ out)
{
    extern __shared__ uint32_t sB[];               // [64 pixels][BSTRIDE kpairs]

    const int tid  = threadIdx.x;
    const int lane = tid & 31;
    const int w    = tid >> 5;
    const int g    = lane >> 2, i4 = lane & 3;

    const int p0 = blockIdx.x * PTILE;
    const int b  = blockIdx.y;

    const float* mfb  = mf  + (size_t)b * HID * NPIX;
    float*       outb = out + (size_t)b * QN  * NPIX;

    // ---- load + convert B tile: 64 pixels x 256 channels, fp32 -> fp16 ----
    for (int idx = tid; idx < 128 * 16; idx += GTHREADS) {
        const int cp  = idx >> 4;
        const int p4  = idx & 15;
        const float* r0 = mfb + (size_t)(2 * cp)     * NPIX + p0 + p4 * 4;
        const float* r1 = mfb + (size_t)(2 * cp + 1) * NPIX + p0 + p4 * 4;
        float4 v0 = *reinterpret_cast<const float4*>(r0);
        float4 v1 = *reinterpret_cast<const float4*>(r1);
        const float a0[4] = {v0.x, v0.y, v0.z, v0.w};
        const float a1[4] = {v1.x, v1.y, v1.z, v1.w};
        #pragma unroll
        for (int s = 0; s < 4; s++) {
            const int j = (s + p4) & 3;            // stagger -> fewer store conflicts
            sB[(uint32_t)(p4 * 4 + j) * BSTRIDE + cp] = pack_f16(a0[j], a1[j]);
        }
    }
    __syncthreads();

    // ---- role assignment (rotated across CTAs) ----
    const int wr    = (w + (int)blockIdx.x) % NWARP;
    const bool dual = (wr < 12);
    const int mr0   = dual ? 2 * (wr >> 1) : 12;
    const int ncb   = dual ? (wr & 1) * 4 : 0;

    // ldmatrix per-thread base
    const int q8 = lane >> 3;
    const int r8 = lane & 7;
    const uint32_t sB_s = (uint32_t)__cvta_generic_to_shared(sB);
    const uint32_t lm_base = sB_s +
        (uint32_t)((((q8 >> 1) * 8 + r8) * BSTRIDE + (q8 & 1) * 4) * 4);
    const uint32_t J_STRIDE = (uint32_t)(16 * BSTRIDE * 4);

    if (dual) {
        // ---------------- dual path: straight-line, no inner branches ------
        float acc0[4][4] = {};
        float acc1[4][4] = {};
        const uint4* pAH0 = g_AH + ((size_t)(b * MROWS + mr0)     * KSTEPS) * 32 + lane;
        const uint4* pAH1 = g_AH + ((size_t)(b * MROWS + mr0 + 1) * KSTEPS) * 32 + lane;
        const uint32_t base = lm_base + (uint32_t)(ncb >> 1) * J_STRIDE;

        #pragma unroll 4
        for (int ks = 0; ks < KSTEPS; ks++) {
            const uint4 ah0 = pAH0[ks * 32];
            const uint4 ah1 = pAH1[ks * 32];
            const uint32_t ka = base + (uint32_t)(ks * 32);
            uint32_t b0, b1, b2, b3, c0, c1, c2, c3;
            ldsm_x4(b0, b1, b2, b3, ka);
            ldsm_x4(c0, c1, c2, c3, ka + J_STRIDE);
            mma_f16(acc0[0], ah0, b0, b1);
            mma_f16(acc0[1], ah0, b2, b3);
            mma_f16(acc1[0], ah1, b0, b1);
            mma_f16(acc1[1], ah1, b2, b3);
            mma_f16(acc0[2], ah0, c0, c1);
            mma_f16(acc0[3], ah0, c2, c3);
            mma_f16(acc1[2], ah1, c0, c1);
            mma_f16(acc1[3], ah1, c2, c3);
        }

        // epilogue: acc0 -> tile mr0, acc1 -> tile mr0+1, n-chunks ncb..ncb+3
        #pragma unroll
        for (int m = 0; m < 2; m++) {
            const float (*am)[4] = m ? acc1 : acc0;
            const int q = (mr0 + m) * 16 + g;
            if (q < QN) {
                float* o = outb + (size_t)q * NPIX + p0 + ncb * 8 + i4 * 2;
                #pragma unroll
                for (int j = 0; j < 4; j++)
                    *reinterpret_cast<float2*>(o + j * 8) = make_float2(am[j][0], am[j][1]);
            }
            const int q2 = q + 8;
            if (q2 < QN) {
                float* o2 = outb + (size_t)q2 * NPIX + p0 + ncb * 8 + i4 * 2;
                #pragma unroll
                for (int j = 0; j < 4; j++)
                    *reinterpret_cast<float2*>(o2 + j * 8) = make_float2(am[j][2], am[j][3]);
            }
        }
    } else {
        // ---------------- single path: R10-exact loop (tile 12) ------------
        float acc[8][4];
        #pragma unroll
        for (int n = 0; n < 8; n++)
            #pragma unroll
            for (int x = 0; x < 4; x++) acc[n][x] = 0.f;

        const uint4* pAH = g_AH + ((size_t)(b * MROWS + mr0) * KSTEPS) * 32 + lane;

        #pragma unroll 4
        for (int ks = 0; ks < KSTEPS; ks++) {
            const uint4 ah = pAH[ks * 32];
            const uint32_t ka = lm_base + (uint32_t)(ks * 32);
            #pragma unroll
            for (int j = 0; j < 4; j++) {
                uint32_t b0, b1, b2, b3;
                ldsm_x4(b0, b1, b2, b3, ka + (uint32_t)j * J_STRIDE);
                mma_f16(acc[2 * j],     ah, b0, b1);
                mma_f16(acc[2 * j + 1], ah, b2, b3);
            }
        }

        const int q = mr0 * 16 + g;
        if (q < QN) {
            float* o = outb + (size_t)q * NPIX + p0 + i4 * 2;
            #pragma unroll
            for (int nc = 0; nc < 8; nc++)
                *reinterpret_cast<float2*>(o + nc * 8) = make_float2(acc[nc][0], acc[nc][1]);
        }
        const int q2 = q + 8;
        if (q2 < QN) {
            float* o2 = outb + (size_t)q2 * NPIX + p0 + i4 * 2;
            #pragma unroll
            for (int nc = 0; nc < 8; nc++)
                *reinterpret_cast<float2*>(o2 + nc * 8) = make_float2(acc[nc][2], acc[nc][3]);
        }
    }
}

// ---------------------------------------------------------------------------
extern "C" void kernel_launch(void* const* d_in, const int* in_sizes, int n_in,
                              void* d_out, int out_size)
{
    const float* queries = (const float*)d_in[0];  // (4, 200, 256)
    const float* mf      = (const float*)d_in[1];  // (4, 256, 256, 256)
    const float* w1      = (const float*)d_in[2];
    const float* b1      = (const float*)d_in[3];
    const float* w2      = (const float*)d_in[4];
    const float* b2      = (const float*)d_in[5];
    float* out = (float*)d_out;                    // (4, 200, 256, 256)

    float* hbuf;  cudaGetSymbolAddress((void**)&hbuf,  g_h);
    float* mebuf; cudaGetSymbolAddress((void**)&mebuf, g_me);

    const int lsm = 2 * HID * LSTRIDE * (int)sizeof(float);     // 73728 B
    cudaFuncSetAttribute(layer_kernel<true >, cudaFuncAttributeMaxDynamicSharedMemorySize, lsm);
    cudaFuncSetAttribute(layer_kernel<false>, cudaFuncAttributeMaxDynamicSharedMemorySize, lsm);

    const int smem = PTILE * BSTRIDE * (int)sizeof(uint32_t);   // 33792 B
    cudaFuncSetAttribute(gemm_kernel, cudaFuncAttributeMaxDynamicSharedMemorySize, smem);

    layer_kernel<true ><<<dim3(NROW / 32, HID / 32), 128, lsm>>>(queries, w1, b1, hbuf);
    layer_kernel<false><<<dim3(NROW / 32, HID / 32), 128, lsm>>>(hbuf,    w2, b2, mebuf);
    pack_kernel<<<NB * MROWS, 512>>>();
    gemm_kernel<<<dim3(NPIX / PTILE, NB), GTHREADS, smem>>>(mf, out);
}